// round 8
// baseline (speedup 1.0000x reference)
#include <cuda_runtime.h>

// ---------------------------------------------------------------------------
// 2-layer GCN: out = S(relu(S(xW1)+b1) W2) + b2, S = D^-1/2 (A+I) D^-1/2
// N=100000 nodes, E=1600000 edges, 128 -> 128 -> 64 features, all fp32.
// Aggregation via on-device CSR + warp-per-node gather (no fp atomics).
// edge_index dtype (int32 vs int64) detected on device.
// ---------------------------------------------------------------------------

#define NN 100000
#define NE 1600000
#define NF 128
#define NH 128
#define NO 64

#define SCAN_B 512
#define SCAN_NBLK ((NN + SCAN_B - 1) / SCAN_B)   // 196

// Scratch (static __device__ per harness rules)
__device__ int   g_is64;                // 1 if edge_index is int64
__device__ int   g_deg[NN];             // edge in-degree (excl. self-loop)
__device__ float g_dinv[NN];            // rsqrt(deg+1)
__device__ int   g_off[NN];             // CSR offsets (exclusive scan of deg)
__device__ int   g_cur[NN];             // fill cursors
__device__ int   g_csr[NE];             // neighbor (src) list grouped by dst
__device__ int   g_bsum[256];           // block sums for scan
__device__ float g_h1[NN * NH];         // x @ W1
__device__ float g_agg1[NN * NH];       // relu(S h1 + b1)
__device__ float g_h2[NN * NO];         // agg1 @ W2

// ---------------- dtype detection (device-side, deterministic) -------------
// int32 data reinterpreted as int64 has a random index in the high 32 bits;
// a genuine int64 index is in [0, NN). 8 words => false-positive ~1e-40.

__global__ void k_detect(const long long* __restrict__ ei) {
    if (threadIdx.x != 0 || blockIdx.x != 0) return;
    int ok = 1;
    for (int i = 0; i < 8; i++) {
        long long v = ei[i];
        if (v < 0 || v >= NN) ok = 0;
    }
    g_is64 = ok;
}

__device__ __forceinline__ int load_idx(const void* ei, long long pos) {
    if (g_is64) return (int)((const long long*)ei)[pos];
    return ((const int*)ei)[pos];
}

// ---------------- degree count ----------------

__global__ void k_deg_zero() {
    int i = blockIdx.x * blockDim.x + threadIdx.x;
    if (i < NN) g_deg[i] = 0;
}

__global__ void k_deg_count(const void* __restrict__ ei) {
    int i = blockIdx.x * blockDim.x + threadIdx.x;
    if (i >= NE) return;
    int d = load_idx(ei, (long long)NE + i);      // dst row
    if ((unsigned)d < NN) atomicAdd(&g_deg[d], 1);
}

// ---------------- 3-pass exclusive scan of g_deg -> g_off ----------------

__global__ void k_scan_block() {
    __shared__ int sm[SCAN_B];
    int i = blockIdx.x * SCAN_B + threadIdx.x;
    sm[threadIdx.x] = (i < NN) ? g_deg[i] : 0;
    __syncthreads();
    for (int s = SCAN_B / 2; s > 0; s >>= 1) {
        if (threadIdx.x < s) sm[threadIdx.x] += sm[threadIdx.x + s];
        __syncthreads();
    }
    if (threadIdx.x == 0) g_bsum[blockIdx.x] = sm[0];
}

__global__ void k_scan_top() {       // 1 block, 256 threads
    __shared__ int sm[256];
    int tid = threadIdx.x;
    int v = (tid < SCAN_NBLK) ? g_bsum[tid] : 0;
    sm[tid] = v;
    __syncthreads();
    for (int d = 1; d < 256; d <<= 1) {
        int t = (tid >= d) ? sm[tid - d] : 0;
        __syncthreads();
        sm[tid] += t;
        __syncthreads();
    }
    g_bsum[tid] = sm[tid] - v;       // exclusive
}

__global__ void k_scan_write() {
    __shared__ int sm[SCAN_B];
    int tid = threadIdx.x;
    int i = blockIdx.x * SCAN_B + tid;
    int v = (i < NN) ? g_deg[i] : 0;
    sm[tid] = v;
    __syncthreads();
    for (int d = 1; d < SCAN_B; d <<= 1) {
        int t = (tid >= d) ? sm[tid - d] : 0;
        __syncthreads();
        sm[tid] += t;
        __syncthreads();
    }
    if (i < NN) {
        g_off[i]  = sm[tid] - v + g_bsum[blockIdx.x];
        g_cur[i]  = 0;
        g_dinv[i] = rsqrtf((float)(v + 1));     // +1 self-loop
    }
}

// ---------------- CSR fill ----------------

__global__ void k_fill(const void* __restrict__ ei) {
    int e = blockIdx.x * blockDim.x + threadIdx.x;
    if (e >= NE) return;
    int s = load_idx(ei, e);
    int d = load_idx(ei, (long long)NE + e);
    if ((unsigned)s >= NN || (unsigned)d >= NN) return;
    int p = atomicAdd(&g_cur[d], 1);
    g_csr[g_off[d] + p] = s;
}

// ---------------- GEMM 1: h1 = x @ W1  (128 -> 128) ----------------
// One warp per row. x row as one float4 per lane, broadcast x[k] via shfl;
// W rows as float4 per lane (64 KB, L1-resident).

__global__ void k_gemm1(const float* __restrict__ X, const float* __restrict__ W) {
    int warp = (blockIdx.x * blockDim.x + threadIdx.x) >> 5;
    if (warp >= NN) return;
    int lane = threadIdx.x & 31;

    float4 xv = ((const float4*)X)[warp * 32 + lane];
    float4 acc = make_float4(0.f, 0.f, 0.f, 0.f);
    const float4* W4 = (const float4*)W;

#pragma unroll
    for (int k = 0; k < NF; k++) {
        float comp = (k & 3) == 0 ? xv.x : (k & 3) == 1 ? xv.y : (k & 3) == 2 ? xv.z : xv.w;
        float xs = __shfl_sync(0xffffffffu, comp, k >> 2);
        float4 w = __ldg(&W4[k * 32 + lane]);
        acc.x = fmaf(xs, w.x, acc.x);
        acc.y = fmaf(xs, w.y, acc.y);
        acc.z = fmaf(xs, w.z, acc.z);
        acc.w = fmaf(xs, w.w, acc.w);
    }
    ((float4*)g_h1)[warp * 32 + lane] = acc;
}

// ---------------- layer-1 aggregation: warp per node, gather over CSR ------
// agg1[d] = relu( dinv[d]^2 * h1[d] + sum_s dinv[s]*dinv[d]*h1[s] + b1 )

__global__ void k_agg1(const float* __restrict__ b1) {
    int node = (blockIdx.x * blockDim.x + threadIdx.x) >> 5;
    if (node >= NN) return;
    int lane = threadIdx.x & 31;

    float dv = g_dinv[node];
    const float4* H = (const float4*)g_h1;

    float4 h = H[node * 32 + lane];
    float w0 = dv * dv;
    float4 acc = make_float4(h.x * w0, h.y * w0, h.z * w0, h.w * w0);

    int beg = g_off[node];
    int end = beg + g_deg[node];
    for (int j = beg; j < end; j++) {
        int s = __ldg(&g_csr[j]);                 // uniform broadcast load
        float w = __ldg(&g_dinv[s]) * dv;
        float4 hv = H[s * 32 + lane];
        acc.x = fmaf(hv.x, w, acc.x);
        acc.y = fmaf(hv.y, w, acc.y);
        acc.z = fmaf(hv.z, w, acc.z);
        acc.w = fmaf(hv.w, w, acc.w);
    }

    float4 bb = ((const float4*)b1)[lane];
    acc.x = fmaxf(acc.x + bb.x, 0.f);
    acc.y = fmaxf(acc.y + bb.y, 0.f);
    acc.z = fmaxf(acc.z + bb.z, 0.f);
    acc.w = fmaxf(acc.w + bb.w, 0.f);
    ((float4*)g_agg1)[node * 32 + lane] = acc;
}

// ---------------- GEMM 2: h2 = agg1 @ W2  (128 -> 64) ----------------

__global__ void k_gemm2(const float* __restrict__ W2) {
    int warp = (blockIdx.x * blockDim.x + threadIdx.x) >> 5;
    if (warp >= NN) return;
    int lane = threadIdx.x & 31;

    float4 xv = ((const float4*)g_agg1)[warp * 32 + lane];
    float2 acc = make_float2(0.f, 0.f);
    const float2* W2v = (const float2*)W2;        // row k: 64 floats = 32 float2

#pragma unroll
    for (int k = 0; k < NH; k++) {
        float comp = (k & 3) == 0 ? xv.x : (k & 3) == 1 ? xv.y : (k & 3) == 2 ? xv.z : xv.w;
        float xs = __shfl_sync(0xffffffffu, comp, k >> 2);
        float2 w = __ldg(&W2v[k * 32 + lane]);
        acc.x = fmaf(xs, w.x, acc.x);
        acc.y = fmaf(xs, w.y, acc.y);
    }
    ((float2*)g_h2)[warp * 32 + lane] = acc;
}

// ---------------- layer-2 aggregation: warp per node (float2 lanes) --------
// out[d] = dinv[d]^2 * h2[d] + sum_s dinv[s]*dinv[d]*h2[s] + b2

__global__ void k_agg2(const float* __restrict__ b2, float* __restrict__ out) {
    int node = (blockIdx.x * blockDim.x + threadIdx.x) >> 5;
    if (node >= NN) return;
    int lane = threadIdx.x & 31;

    float dv = g_dinv[node];
    const float2* H = (const float2*)g_h2;

    float2 h = H[node * 32 + lane];
    float w0 = dv * dv;
    float2 acc = make_float2(h.x * w0, h.y * w0);

    int beg = g_off[node];
    int end = beg + g_deg[node];
    for (int j = beg; j < end; j++) {
        int s = __ldg(&g_csr[j]);
        float w = __ldg(&g_dinv[s]) * dv;
        float2 hv = H[s * 32 + lane];
        acc.x = fmaf(hv.x, w, acc.x);
        acc.y = fmaf(hv.y, w, acc.y);
    }

    float2 bb = ((const float2*)b2)[lane];
    acc.x += bb.x;
    acc.y += bb.y;
    ((float2*)out)[node * 32 + lane] = acc;
}

// ---------------------------------------------------------------------------

extern "C" void kernel_launch(void* const* d_in, const int* in_sizes, int n_in,
                              void* d_out, int out_size) {
    const void* ei = d_in[0];                    // [2, NE] int32 OR int64
    const float* x  = (const float*)d_in[1];
    const float* W1 = (const float*)d_in[2];
    const float* b1 = (const float*)d_in[3];
    const float* W2 = (const float*)d_in[4];
    const float* b2 = (const float*)d_in[5];
    float* out = (float*)d_out;

    // dtype detect + degree + CSR build
    k_detect   <<<1, 32>>>((const long long*)ei);
    k_deg_zero <<<(NN + 255) / 256, 256>>>();
    k_deg_count<<<(NE + 255) / 256, 256>>>(ei);
    k_scan_block<<<SCAN_NBLK, SCAN_B>>>();
    k_scan_top  <<<1, 256>>>();
    k_scan_write<<<SCAN_NBLK, SCAN_B>>>();
    k_fill      <<<(NE + 255) / 256, 256>>>(ei);

    // layer 1
    k_gemm1<<<(NN * 32 + 255) / 256, 256>>>(x, W1);
    k_agg1 <<<(NN * 32 + 255) / 256, 256>>>(b1);

    // layer 2
    k_gemm2<<<(NN * 32 + 255) / 256, 256>>>(W2);
    k_agg2 <<<(NN * 32 + 255) / 256, 256>>>(b2, out);
}

// round 10
// speedup vs baseline: 1.5254x; 1.5254x over previous
#include <cuda_runtime.h>

// ---------------------------------------------------------------------------
// 2-layer GCN: out = S(relu(S(xW1)+b1) W2) + b2, S = D^-1/2 (A+I) D^-1/2
// N=100000 nodes, E=1600000 edges, 128 -> 128 -> 64 features, all fp32.
// CSR gather aggregation (no fp atomics); packed f32x2 FFMA throughout.
// ---------------------------------------------------------------------------

#define NN 100000
#define NE 1600000
#define NF 128
#define NH 128
#define NO 64

#define SCAN_B 512
#define SCAN_NBLK ((NN + SCAN_B - 1) / SCAN_B)   // 196

typedef unsigned long long u64;

__device__ __forceinline__ u64 pack2(float lo, float hi) {
    u64 r; asm("mov.b64 %0, {%1, %2};" : "=l"(r) : "f"(lo), "f"(hi)); return r;
}
__device__ __forceinline__ void unpack2(u64 v, float& lo, float& hi) {
    asm("mov.b64 {%0, %1}, %2;" : "=f"(lo), "=f"(hi) : "l"(v));
}
// d = a*b + d, elementwise on packed fp32 pairs (bit-identical to 2x fmaf)
__device__ __forceinline__ void ffma2(u64& d, u64 a, u64 b) {
    asm("fma.rn.f32x2 %0, %1, %2, %0;" : "+l"(d) : "l"(a), "l"(b));
}

// Scratch (static __device__ per harness rules)
__device__ int   g_is64;                // 1 if edge_index is int64
__device__ int   g_deg[NN];             // edge in-degree (excl. self-loop)
__device__ float g_dinv[NN];            // rsqrt(deg+1)
__device__ int   g_off[NN];             // CSR offsets (exclusive scan of deg)
__device__ int   g_cur[NN];             // fill cursors
__device__ int   g_csr[NE];             // neighbor (src) list grouped by dst
__device__ int   g_bsum[256];           // block sums for scan
__device__ float g_h1[NN * NH];         // x @ W1
__device__ float g_agg1[NN * NH];       // relu(S h1 + b1)
__device__ float g_h2[NN * NO];         // agg1 @ W2

// ---------------- dtype detection (device-side, deterministic) -------------

__global__ void k_detect(const long long* __restrict__ ei) {
    if (threadIdx.x != 0 || blockIdx.x != 0) return;
    int ok = 1;
    for (int i = 0; i < 8; i++) {
        long long v = ei[i];
        if (v < 0 || v >= NN) ok = 0;
    }
    g_is64 = ok;
}

__device__ __forceinline__ int load_idx(const void* ei, long long pos) {
    if (g_is64) return (int)((const long long*)ei)[pos];
    return ((const int*)ei)[pos];
}

// ---------------- degree count ----------------

__global__ void k_deg_zero() {
    int i = blockIdx.x * blockDim.x + threadIdx.x;
    if (i < NN) g_deg[i] = 0;
}

__global__ void k_deg_count(const void* __restrict__ ei) {
    int i = blockIdx.x * blockDim.x + threadIdx.x;
    if (i >= NE) return;
    int d = load_idx(ei, (long long)NE + i);      // dst row
    if ((unsigned)d < NN) atomicAdd(&g_deg[d], 1);
}

// ---------------- 3-pass exclusive scan of g_deg -> g_off ----------------

__global__ void k_scan_block() {
    __shared__ int sm[SCAN_B];
    int i = blockIdx.x * SCAN_B + threadIdx.x;
    sm[threadIdx.x] = (i < NN) ? g_deg[i] : 0;
    __syncthreads();
    for (int s = SCAN_B / 2; s > 0; s >>= 1) {
        if (threadIdx.x < s) sm[threadIdx.x] += sm[threadIdx.x + s];
        __syncthreads();
    }
    if (threadIdx.x == 0) g_bsum[blockIdx.x] = sm[0];
}

__global__ void k_scan_top() {       // 1 block, 256 threads
    __shared__ int sm[256];
    int tid = threadIdx.x;
    int v = (tid < SCAN_NBLK) ? g_bsum[tid] : 0;
    sm[tid] = v;
    __syncthreads();
    for (int d = 1; d < 256; d <<= 1) {
        int t = (tid >= d) ? sm[tid - d] : 0;
        __syncthreads();
        sm[tid] += t;
        __syncthreads();
    }
    g_bsum[tid] = sm[tid] - v;       // exclusive
}

__global__ void k_scan_write() {
    __shared__ int sm[SCAN_B];
    int tid = threadIdx.x;
    int i = blockIdx.x * SCAN_B + tid;
    int v = (i < NN) ? g_deg[i] : 0;
    sm[tid] = v;
    __syncthreads();
    for (int d = 1; d < SCAN_B; d <<= 1) {
        int t = (tid >= d) ? sm[tid - d] : 0;
        __syncthreads();
        sm[tid] += t;
        __syncthreads();
    }
    if (i < NN) {
        g_off[i]  = sm[tid] - v + g_bsum[blockIdx.x];
        g_cur[i]  = 0;
        g_dinv[i] = rsqrtf((float)(v + 1));     // +1 self-loop
    }
}

// ---------------- CSR fill ----------------

__global__ void k_fill(const void* __restrict__ ei) {
    int e = blockIdx.x * blockDim.x + threadIdx.x;
    if (e >= NE) return;
    int s = load_idx(ei, e);
    int d = load_idx(ei, (long long)NE + e);
    if ((unsigned)s >= NN || (unsigned)d >= NN) return;
    int p = atomicAdd(&g_cur[d], 1);
    g_csr[g_off[d] + p] = s;
}

// ---------------- GEMM 1: h1 = x @ W1  (128 -> 128) ----------------
// Warp per row; x row as float4/lane broadcast via shfl; W as ulonglong2
// (packed fp32 pairs) -> 2 FFMA2 per k per lane instead of 4 FFMA.

__global__ void k_gemm1(const float* __restrict__ X, const float* __restrict__ W) {
    int warp = (blockIdx.x * blockDim.x + threadIdx.x) >> 5;
    if (warp >= NN) return;
    int lane = threadIdx.x & 31;

    float4 xv = ((const float4*)X)[warp * 32 + lane];
    const ulonglong2* W4 = (const ulonglong2*)W;
    u64 acc0 = 0, acc1 = 0;

#pragma unroll
    for (int k = 0; k < NF; k++) {
        float comp = (k & 3) == 0 ? xv.x : (k & 3) == 1 ? xv.y : (k & 3) == 2 ? xv.z : xv.w;
        float xs = __shfl_sync(0xffffffffu, comp, k >> 2);
        u64 xx = pack2(xs, xs);
        ulonglong2 w = __ldg(&W4[k * 32 + lane]);
        ffma2(acc0, xx, w.x);
        ffma2(acc1, xx, w.y);
    }
    ((ulonglong2*)g_h1)[warp * 32 + lane] = make_ulonglong2(acc0, acc1);
}

// ---------------- layer-1 aggregation: warp per node, batched gather -------
// Prefetch up to 32 neighbor indices + dinv in parallel across lanes, then
// only the (independent) 512B row gathers remain in the inner loop.

__global__ void k_agg1(const float* __restrict__ b1) {
    int node = (blockIdx.x * blockDim.x + threadIdx.x) >> 5;
    if (node >= NN) return;
    int lane = threadIdx.x & 31;

    float dv = g_dinv[node];
    const ulonglong2* H = (const ulonglong2*)g_h1;

    ulonglong2 h = H[node * 32 + lane];
    u64 w0 = pack2(dv * dv, dv * dv);
    u64 acc0 = 0, acc1 = 0;
    ffma2(acc0, w0, h.x);
    ffma2(acc1, w0, h.y);

    int beg = g_off[node];
    int deg = g_deg[node];
    for (int base = 0; base < deg; base += 32) {
        int n = min(32, deg - base);
        int idx = 0; float wv = 0.f;
        if (lane < n) {
            idx = __ldg(&g_csr[beg + base + lane]);
            wv  = __ldg(&g_dinv[idx]);
        }
#pragma unroll 4
        for (int j = 0; j < n; j++) {
            int s   = __shfl_sync(0xffffffffu, idx, j);
            float w = __shfl_sync(0xffffffffu, wv, j) * dv;
            u64 ww = pack2(w, w);
            ulonglong2 hv = H[s * 32 + lane];
            ffma2(acc0, ww, hv.x);
            ffma2(acc1, ww, hv.y);
        }
    }

    float4 bb = ((const float4*)b1)[lane];
    float a0, a1, a2, a3;
    unpack2(acc0, a0, a1);
    unpack2(acc1, a2, a3);
    float4 r;
    r.x = fmaxf(a0 + bb.x, 0.f);
    r.y = fmaxf(a1 + bb.y, 0.f);
    r.z = fmaxf(a2 + bb.z, 0.f);
    r.w = fmaxf(a3 + bb.w, 0.f);
    ((float4*)g_agg1)[node * 32 + lane] = r;
}

// ---------------- GEMM 2: h2 = agg1 @ W2  (128 -> 64) ----------------

__global__ void k_gemm2(const float* __restrict__ W2) {
    int warp = (blockIdx.x * blockDim.x + threadIdx.x) >> 5;
    if (warp >= NN) return;
    int lane = threadIdx.x & 31;

    float4 xv = ((const float4*)g_agg1)[warp * 32 + lane];
    const u64* W2v = (const u64*)W2;      // row k: 64 floats = 32 packed pairs
    u64 acc = 0;

#pragma unroll
    for (int k = 0; k < NH; k++) {
        float comp = (k & 3) == 0 ? xv.x : (k & 3) == 1 ? xv.y : (k & 3) == 2 ? xv.z : xv.w;
        float xs = __shfl_sync(0xffffffffu, comp, k >> 2);
        u64 xx = pack2(xs, xs);
        u64 w = __ldg(&W2v[k * 32 + lane]);
        ffma2(acc, xx, w);
    }
    ((u64*)g_h2)[warp * 32 + lane] = acc;
}

// ---------------- layer-2 aggregation: warp per node (float2 lanes) --------

__global__ void k_agg2(const float* __restrict__ b2, float* __restrict__ out) {
    int node = (blockIdx.x * blockDim.x + threadIdx.x) >> 5;
    if (node >= NN) return;
    int lane = threadIdx.x & 31;

    float dv = g_dinv[node];
    const u64* H = (const u64*)g_h2;

    u64 h = H[node * 32 + lane];
    u64 w0 = pack2(dv * dv, dv * dv);
    u64 acc = 0;
    ffma2(acc, w0, h);

    int beg = g_off[node];
    int deg = g_deg[node];
    for (int base = 0; base < deg; base += 32) {
        int n = min(32, deg - base);
        int idx = 0; float wv = 0.f;
        if (lane < n) {
            idx = __ldg(&g_csr[beg + base + lane]);
            wv  = __ldg(&g_dinv[idx]);
        }
#pragma unroll 4
        for (int j = 0; j < n; j++) {
            int s   = __shfl_sync(0xffffffffu, idx, j);
            float w = __shfl_sync(0xffffffffu, wv, j) * dv;
            u64 ww = pack2(w, w);
            u64 hv = H[s * 32 + lane];
            ffma2(acc, ww, hv);
        }
    }

    float2 bb = ((const float2*)b2)[lane];
    float a0, a1;
    unpack2(acc, a0, a1);
    float2 r;
    r.x = a0 + bb.x;
    r.y = a1 + bb.y;
    ((float2*)out)[node * 32 + lane] = r;
}

// ---------------------------------------------------------------------------

extern "C" void kernel_launch(void* const* d_in, const int* in_sizes, int n_in,
                              void* d_out, int out_size) {
    const void* ei = d_in[0];                    // [2, NE] int32 OR int64
    const float* x  = (const float*)d_in[1];
    const float* W1 = (const float*)d_in[2];
    const float* b1 = (const float*)d_in[3];
    const float* W2 = (const float*)d_in[4];
    const float* b2 = (const float*)d_in[5];
    float* out = (float*)d_out;

    // dtype detect + degree + CSR build
    k_detect   <<<1, 32>>>((const long long*)ei);
    k_deg_zero <<<(NN + 255) / 256, 256>>>();
    k_deg_count<<<(NE + 255) / 256, 256>>>(ei);
    k_scan_block<<<SCAN_NBLK, SCAN_B>>>();
    k_scan_top  <<<1, 256>>>();
    k_scan_write<<<SCAN_NBLK, SCAN_B>>>();
    k_fill      <<<(NE + 255) / 256, 256>>>(ei);

    // layer 1
    k_gemm1<<<(NN * 32 + 255) / 256, 256>>>(x, W1);
    k_agg1 <<<(NN * 32 + 255) / 256, 256>>>(b1);

    // layer 2
    k_gemm2<<<(NN * 32 + 255) / 256, 256>>>(W2);
    k_agg2 <<<(NN * 32 + 255) / 256, 256>>>(b2, out);
}

// round 11
// speedup vs baseline: 1.5974x; 1.0472x over previous
#include <cuda_runtime.h>

// ---------------------------------------------------------------------------
// 2-layer GCN: out = S(relu(S(xW1)+b1) W2) + b2, S = D^-1/2 (A+I) D^-1/2
// N=100000 nodes, E=1600000 edges, 128 -> 128 -> 64 features, all fp32.
// CSR gather aggregation (no fp atomics); packed f32x2 FFMA throughout.
// Layer-1 aggregation fused with GEMM2 (row stays in registers).
// ---------------------------------------------------------------------------

#define NN 100000
#define NE 1600000
#define NF 128
#define NH 128
#define NO 64

#define SCAN_B 512
#define SCAN_NBLK ((NN + SCAN_B - 1) / SCAN_B)   // 196

typedef unsigned long long u64;

__device__ __forceinline__ u64 pack2(float lo, float hi) {
    u64 r; asm("mov.b64 %0, {%1, %2};" : "=l"(r) : "f"(lo), "f"(hi)); return r;
}
__device__ __forceinline__ void unpack2(u64 v, float& lo, float& hi) {
    asm("mov.b64 {%0, %1}, %2;" : "=f"(lo), "=f"(hi) : "l"(v));
}
// d = a*b + d, elementwise on packed fp32 pairs (bit-identical to 2x fmaf)
__device__ __forceinline__ void ffma2(u64& d, u64 a, u64 b) {
    asm("fma.rn.f32x2 %0, %1, %2, %0;" : "+l"(d) : "l"(a), "l"(b));
}

// Scratch (static __device__ per harness rules)
__device__ int   g_is64;                // 1 if edge_index is int64
__device__ int   g_deg[NN];             // edge in-degree (excl. self-loop)
__device__ float g_dinv[NN];            // rsqrt(deg+1)
__device__ int   g_off[NN];             // CSR offsets (exclusive scan of deg)
__device__ int   g_pos[NE];             // per-edge slot within its dst bucket
__device__ int   g_csr[NE];             // neighbor (src) list grouped by dst
__device__ int   g_bsum[256];           // block sums for scan
__device__ float g_h1[NN * NH];         // x @ W1
__device__ float g_h2[NN * NO];         // relu(S h1 + b1) @ W2

// ---------------- dtype detection (device-side, deterministic) -------------

__global__ void k_detect(const long long* __restrict__ ei) {
    if (threadIdx.x != 0 || blockIdx.x != 0) return;
    int ok = 1;
    for (int i = 0; i < 8; i++) {
        long long v = ei[i];
        if (v < 0 || v >= NN) ok = 0;
    }
    g_is64 = ok;
}

__device__ __forceinline__ int load_idx(const void* ei, long long pos) {
    if (g_is64) return (int)((const long long*)ei)[pos];
    return ((const int*)ei)[pos];
}

// ---------------- degree count (atomic return = CSR slot) ----------------

__global__ void k_deg_zero() {
    int i = blockIdx.x * blockDim.x + threadIdx.x;
    if (i < NN) g_deg[i] = 0;
}

__global__ void k_deg_count(const void* __restrict__ ei) {
    int i = blockIdx.x * blockDim.x + threadIdx.x;
    if (i >= NE) return;
    int d = load_idx(ei, (long long)NE + i);      // dst row
    if ((unsigned)d < NN) g_pos[i] = atomicAdd(&g_deg[d], 1);
}

// ---------------- 3-pass exclusive scan of g_deg -> g_off ----------------

__global__ void k_scan_block() {
    __shared__ int sm[SCAN_B];
    int i = blockIdx.x * SCAN_B + threadIdx.x;
    sm[threadIdx.x] = (i < NN) ? g_deg[i] : 0;
    __syncthreads();
    for (int s = SCAN_B / 2; s > 0; s >>= 1) {
        if (threadIdx.x < s) sm[threadIdx.x] += sm[threadIdx.x + s];
        __syncthreads();
    }
    if (threadIdx.x == 0) g_bsum[blockIdx.x] = sm[0];
}

__global__ void k_scan_top() {       // 1 block, 256 threads
    __shared__ int sm[256];
    int tid = threadIdx.x;
    int v = (tid < SCAN_NBLK) ? g_bsum[tid] : 0;
    sm[tid] = v;
    __syncthreads();
    for (int d = 1; d < 256; d <<= 1) {
        int t = (tid >= d) ? sm[tid - d] : 0;
        __syncthreads();
        sm[tid] += t;
        __syncthreads();
    }
    g_bsum[tid] = sm[tid] - v;       // exclusive
}

__global__ void k_scan_write() {
    __shared__ int sm[SCAN_B];
    int tid = threadIdx.x;
    int i = blockIdx.x * SCAN_B + tid;
    int v = (i < NN) ? g_deg[i] : 0;
    sm[tid] = v;
    __syncthreads();
    for (int d = 1; d < SCAN_B; d <<= 1) {
        int t = (tid >= d) ? sm[tid - d] : 0;
        __syncthreads();
        sm[tid] += t;
        __syncthreads();
    }
    if (i < NN) {
        g_off[i]  = sm[tid] - v + g_bsum[blockIdx.x];
        g_dinv[i] = rsqrtf((float)(v + 1));     // +1 self-loop
    }
}

// ---------------- CSR fill (no atomics: slot precomputed) ----------------

__global__ void k_fill(const void* __restrict__ ei) {
    int e = blockIdx.x * blockDim.x + threadIdx.x;
    if (e >= NE) return;
    int s = load_idx(ei, e);
    int d = load_idx(ei, (long long)NE + e);
    if ((unsigned)s >= NN || (unsigned)d >= NN) return;
    g_csr[g_off[d] + g_pos[e]] = s;
}

// ---------------- GEMM 1: h1 = x @ W1  (128 -> 128) ----------------
// Warp per row; x row as float4/lane broadcast via shfl; W as ulonglong2
// (packed fp32 pairs) -> 2 FFMA2 per k per lane instead of 4 FFMA.

__global__ void k_gemm1(const float* __restrict__ X, const float* __restrict__ W) {
    int warp = (blockIdx.x * blockDim.x + threadIdx.x) >> 5;
    if (warp >= NN) return;
    int lane = threadIdx.x & 31;

    float4 xv = ((const float4*)X)[warp * 32 + lane];
    const ulonglong2* W4 = (const ulonglong2*)W;
    u64 acc0 = 0, acc1 = 0;

#pragma unroll
    for (int k = 0; k < NF; k++) {
        float comp = (k & 3) == 0 ? xv.x : (k & 3) == 1 ? xv.y : (k & 3) == 2 ? xv.z : xv.w;
        float xs = __shfl_sync(0xffffffffu, comp, k >> 2);
        u64 xx = pack2(xs, xs);
        ulonglong2 w = __ldg(&W4[k * 32 + lane]);
        ffma2(acc0, xx, w.x);
        ffma2(acc1, xx, w.y);
    }
    ((ulonglong2*)g_h1)[warp * 32 + lane] = make_ulonglong2(acc0, acc1);
}

// ---------------- fused layer-1 agg + GEMM2 ----------------
// Warp per node: gather-aggregate over CSR into registers, apply bias+relu,
// then immediately multiply the register-resident row by W2 -> h2.
// Saves the 51MB agg1 store + 51MB reload entirely.

__global__ void k_l1fused(const float* __restrict__ b1, const float* __restrict__ W2) {
    int node = (blockIdx.x * blockDim.x + threadIdx.x) >> 5;
    if (node >= NN) return;
    int lane = threadIdx.x & 31;

    float dv = g_dinv[node];
    const ulonglong2* H = (const ulonglong2*)g_h1;

    ulonglong2 h = H[node * 32 + lane];
    u64 w0 = pack2(dv * dv, dv * dv);
    u64 acc0 = 0, acc1 = 0;
    ffma2(acc0, w0, h.x);
    ffma2(acc1, w0, h.y);

    int beg = g_off[node];
    int deg = g_deg[node];
    for (int base = 0; base < deg; base += 32) {
        int n = min(32, deg - base);
        int idx = 0; float wv = 0.f;
        if (lane < n) {
            idx = __ldg(&g_csr[beg + base + lane]);
            wv  = __ldg(&g_dinv[idx]);
        }
#pragma unroll 8
        for (int j = 0; j < n; j++) {
            int s   = __shfl_sync(0xffffffffu, idx, j);
            float w = __shfl_sync(0xffffffffu, wv, j) * dv;
            u64 ww = pack2(w, w);
            ulonglong2 hv = H[s * 32 + lane];
            ffma2(acc0, ww, hv.x);
            ffma2(acc1, ww, hv.y);
        }
    }

    float4 bb = ((const float4*)b1)[lane];
    float a0, a1, a2, a3;
    unpack2(acc0, a0, a1);
    unpack2(acc1, a2, a3);
    float4 xv;
    xv.x = fmaxf(a0 + bb.x, 0.f);
    xv.y = fmaxf(a1 + bb.y, 0.f);
    xv.z = fmaxf(a2 + bb.z, 0.f);
    xv.w = fmaxf(a3 + bb.w, 0.f);

    // ---- GEMM2 on the register-resident row: h2 = row @ W2 (128 -> 64) ----
    const u64* W2v = (const u64*)W2;      // row k: 64 floats = 32 packed pairs
    u64 acc = 0;
#pragma unroll
    for (int k = 0; k < NH; k++) {
        float comp = (k & 3) == 0 ? xv.x : (k & 3) == 1 ? xv.y : (k & 3) == 2 ? xv.z : xv.w;
        float xs = __shfl_sync(0xffffffffu, comp, k >> 2);
        u64 xx = pack2(xs, xs);
        u64 w = __ldg(&W2v[k * 32 + lane]);
        ffma2(acc, xx, w);
    }
    ((u64*)g_h2)[node * 32 + lane] = acc;
}

// ---------------- layer-2 aggregation: warp per node (float2 lanes) --------

__global__ void k_agg2(const float* __restrict__ b2, float* __restrict__ out) {
    int node = (blockIdx.x * blockDim.x + threadIdx.x) >> 5;
    if (node >= NN) return;
    int lane = threadIdx.x & 31;

    float dv = g_dinv[node];
    const u64* H = (const u64*)g_h2;

    u64 h = H[node * 32 + lane];
    u64 w0 = pack2(dv * dv, dv * dv);
    u64 acc = 0;
    ffma2(acc, w0, h);

    int beg = g_off[node];
    int deg = g_deg[node];
    for (int base = 0; base < deg; base += 32) {
        int n = min(32, deg - base);
        int idx = 0; float wv = 0.f;
        if (lane < n) {
            idx = __ldg(&g_csr[beg + base + lane]);
            wv  = __ldg(&g_dinv[idx]);
        }
#pragma unroll 8
        for (int j = 0; j < n; j++) {
            int s   = __shfl_sync(0xffffffffu, idx, j);
            float w = __shfl_sync(0xffffffffu, wv, j) * dv;
            u64 ww = pack2(w, w);
            u64 hv = H[s * 32 + lane];
            ffma2(acc, ww, hv);
        }
    }

    float2 bb = ((const float2*)b2)[lane];
    float a0, a1;
    unpack2(acc, a0, a1);
    float2 r;
    r.x = a0 + bb.x;
    r.y = a1 + bb.y;
    ((float2*)out)[node * 32 + lane] = r;
}

// ---------------------------------------------------------------------------

extern "C" void kernel_launch(void* const* d_in, const int* in_sizes, int n_in,
                              void* d_out, int out_size) {
    const void* ei = d_in[0];                    // [2, NE] int32 OR int64
    const float* x  = (const float*)d_in[1];
    const float* W1 = (const float*)d_in[2];
    const float* b1 = (const float*)d_in[3];
    const float* W2 = (const float*)d_in[4];
    const float* b2 = (const float*)d_in[5];
    float* out = (float*)d_out;

    // CSR build interleaved with gemm1 (gemm1 placed at launch index 5 so the
    // ncu -s 5 -c 1 window profiles a kernel that matters)
    k_detect    <<<1, 32>>>((const long long*)ei);            // 0
    k_deg_zero  <<<(NN + 255) / 256, 256>>>();                // 1
    k_deg_count <<<(NE + 255) / 256, 256>>>(ei);              // 2
    k_scan_block<<<SCAN_NBLK, SCAN_B>>>();                    // 3
    k_scan_top  <<<1, 256>>>();                               // 4
    k_gemm1     <<<(NN * 32 + 255) / 256, 256>>>(x, W1);      // 5  <- profiled
    k_scan_write<<<SCAN_NBLK, SCAN_B>>>();                    // 6
    k_fill      <<<(NE + 255) / 256, 256>>>(ei);              // 7

    // layer 1 agg + gemm2 fused, then layer 2 agg
    k_l1fused<<<(NN * 32 + 255) / 256, 256>>>(b1, W2);        // 8
    k_agg2   <<<(NN * 32 + 255) / 256, 256>>>(b2, out);       // 9
}